// round 13
// baseline (speedup 1.0000x reference)
#include <cuda_runtime.h>
#include <cuda_bf16.h>
#include <cstdint>

// Problem constants
#define B_   1024
#define N_   32
#define D_   512
#define H_   4
#define HD_  128
#define QKV_COLS 1536
#define M_ROWS   32768
#define KT   1536              // logical K (3 * 512): [Ah|Al|Ah] x [Bh|Bh|Bl]
#define KTA  1024              // A-side physical stride: [Ah|Al] (region 3 = region 1)

// GEMM tiling (round-9 proven config)
#define BM 128
#define BN 128
#define BK 32                       // bf16 per K-chunk (64B data per row)
#define STAGES 4
#define ROWB 80                     // smem row stride bytes (64 data + 16 pad)
#define A_ST (BM * ROWB)            // 10240
#define ST_BYTES (2 * A_ST)         // 20480 (A tile + B tile)
#define GEMM_SMEM (STAGES * ST_BYTES)  // 81920
#define NK (KT / BK)                // 48

// Scratch (device globals — allocation-free per harness rules)
__device__ float         g_qkv [(size_t)M_ROWS * QKV_COLS];  // fp32 (B*N,1536)
__device__ __nv_bfloat16 g_xa  [(size_t)M_ROWS * KTA];       // x  split [Ah|Al]
__device__ __nv_bfloat16 g_ctxa[(size_t)M_ROWS * KTA];       // ctx split [ch|cl]
__device__ __nv_bfloat16 g_wina[(size_t)QKV_COLS * KT];      // W_in  split [Bh|Bh|Bl]
__device__ __nv_bfloat16 g_wouta[(size_t)D_ * KT];           // W_out split [Bh|Bh|Bl]

// ---------------------------------------------------------------------------
// PTX helpers (all arch-agnostic: cp.async / ldmatrix / mma.sync)
// ---------------------------------------------------------------------------
__device__ __forceinline__ uint32_t smem_u32(const void* p) {
    uint32_t a;
    asm("{ .reg .u64 t; cvta.to.shared.u64 t, %1; cvt.u32.u64 %0, t; }"
        : "=r"(a) : "l"(p));
    return a;
}

__device__ __forceinline__ void cp_async16(uint32_t s, const void* g) {
    asm volatile("cp.async.cg.shared.global [%0], [%1], 16;"
                 :: "r"(s), "l"(g) : "memory");
}
#define CP_COMMIT() asm volatile("cp.async.commit_group;" ::: "memory")
#define CP_WAIT(n)  asm volatile("cp.async.wait_group %0;" :: "n"(n) : "memory")

__device__ __forceinline__ void ldsm4(uint32_t* r, uint32_t addr) {
    asm volatile("ldmatrix.sync.aligned.m8n8.x4.shared.b16 {%0,%1,%2,%3}, [%4];"
                 : "=r"(r[0]), "=r"(r[1]), "=r"(r[2]), "=r"(r[3]) : "r"(addr));
}

__device__ __forceinline__ void mma16816(float* d, const uint32_t* a,
                                         const uint32_t* b) {
    asm volatile("mma.sync.aligned.m16n8k16.row.col.f32.bf16.bf16.f32 "
                 "{%0,%1,%2,%3}, {%4,%5,%6,%7}, {%8,%9}, {%0,%1,%2,%3};"
                 : "+f"(d[0]), "+f"(d[1]), "+f"(d[2]), "+f"(d[3])
                 : "r"(a[0]), "r"(a[1]), "r"(a[2]), "r"(a[3]),
                   "r"(b[0]), "r"(b[1]));
}

// ---------------------------------------------------------------------------
// Split-precision conversion kernels
// ---------------------------------------------------------------------------
__device__ __forceinline__ void split_bf16(float v, __nv_bfloat16& hi, __nv_bfloat16& lo) {
    hi = __float2bfloat16_rn(v);
    lo = __float2bfloat16_rn(v - __bfloat162float(hi));
}

// A-side layout: [Ah | Al] (stride KTA)
__global__ void conv_a(const float* __restrict__ src, __nv_bfloat16* __restrict__ dst,
                       int total4) {
    int idx = blockIdx.x * 256 + threadIdx.x;
    if (idx >= total4) return;
    int row = idx >> 7;            // 128 float4 per 512-col row
    int c4  = (idx & 127) << 2;
    float4 v = *(const float4*)(src + (size_t)row * 512 + c4);
    __nv_bfloat16 h0, h1, h2, h3, l0, l1, l2, l3;
    split_bf16(v.x, h0, l0); split_bf16(v.y, h1, l1);
    split_bf16(v.z, h2, l2); split_bf16(v.w, h3, l3);
    __nv_bfloat16* d = dst + (size_t)row * KTA + c4;
    ((__nv_bfloat162*)(d       ))[0] = __nv_bfloat162(h0, h1);
    ((__nv_bfloat162*)(d       ))[1] = __nv_bfloat162(h2, h3);
    ((__nv_bfloat162*)(d +  512))[0] = __nv_bfloat162(l0, l1);
    ((__nv_bfloat162*)(d +  512))[1] = __nv_bfloat162(l2, l3);
}

// B-side layout: [Bh | Bh | Bl] (stride KT)
__global__ void conv_b(const float* __restrict__ src, __nv_bfloat16* __restrict__ dst,
                       int total4) {
    int idx = blockIdx.x * 256 + threadIdx.x;
    if (idx >= total4) return;
    int row = idx >> 7;
    int c4  = (idx & 127) << 2;
    float4 v = *(const float4*)(src + (size_t)row * 512 + c4);
    __nv_bfloat16 h0, h1, h2, h3, l0, l1, l2, l3;
    split_bf16(v.x, h0, l0); split_bf16(v.y, h1, l1);
    split_bf16(v.z, h2, l2); split_bf16(v.w, h3, l3);
    __nv_bfloat16* d = dst + (size_t)row * KT + c4;
    ((__nv_bfloat162*)(d       ))[0] = __nv_bfloat162(h0, h1);
    ((__nv_bfloat162*)(d       ))[1] = __nv_bfloat162(h2, h3);
    ((__nv_bfloat162*)(d +  512))[0] = __nv_bfloat162(h0, h1);
    ((__nv_bfloat162*)(d +  512))[1] = __nv_bfloat162(h2, h3);
    ((__nv_bfloat162*)(d + 1024))[0] = __nv_bfloat162(l0, l1);
    ((__nv_bfloat162*)(d + 1024))[1] = __nv_bfloat162(l2, l3);
}

// ---------------------------------------------------------------------------
// HMMA GEMM: C[M, Nout](fp32) = A[M, KT](bf16) @ B[Nout, KT](bf16)^T + bias
// Round-9 config: CTA 128x128, 4 warps (2x2), warp tile 64x64, K-chunk 32,
// 4-stage cp.async, 80B row stride, one barrier per K-chunk.
// A is stored deduped ([Ah|Al], stride KTA); logical chunk kc>=32 reads
// physical chunk kc-32 (region 3 == region 1).
// ---------------------------------------------------------------------------
__global__ __launch_bounds__(128, 2)
void gemm_mma(const __nv_bfloat16* __restrict__ A,
              const __nv_bfloat16* __restrict__ Bm,
              const float* __restrict__ bias, float* __restrict__ C, int Nout)
{
    extern __shared__ __align__(128) char smem[];
    const int tid  = threadIdx.x;
    const int wid  = tid >> 5;
    const int lane = tid & 31;
    const int m0 = blockIdx.y * BM;
    const int n0 = blockIdx.x * BN;
    const int warp_m = (wid >> 1) * 64;   // 0 or 64
    const int warp_n = (wid & 1) * 64;    // 0 or 64
    const uint32_t sbase = smem_u32(smem);

    // load thread mapping: 512 16B-chunks per tile, 4 per thread per tile
    const int lr = tid >> 2;        // 0..31 base row
    const int lc = tid & 3;         // 16B chunk in row

    float acc[4][8][4];
#pragma unroll
    for (int mi = 0; mi < 4; mi++)
#pragma unroll
        for (int ni = 0; ni < 8; ni++)
#pragma unroll
            for (int r = 0; r < 4; r++) acc[mi][ni][r] = 0.f;

    auto load_stage = [&](int kc, int buf) {
        const uint32_t as = sbase + buf * ST_BYTES;
        const uint32_t bs = as + A_ST;
        const int kca = (kc < 32) ? kc : kc - 32;   // A region-3 dedup remap
        const __nv_bfloat16* Ag = A  + (size_t)m0 * KTA + kca * BK;
        const __nv_bfloat16* Bg = Bm + (size_t)n0 * KT  + kc  * BK;
#pragma unroll
        for (int i = 0; i < 4; i++) {
            int r = lr + i * 32;
            cp_async16(as + r * ROWB + lc * 16, Ag + (size_t)r * KTA + lc * 8);
        }
#pragma unroll
        for (int i = 0; i < 4; i++) {
            int r = lr + i * 32;
            cp_async16(bs + r * ROWB + lc * 16, Bg + (size_t)r * KT + lc * 8);
        }
        CP_COMMIT();
    };

    load_stage(0, 0);
    load_stage(1, 1);
    load_stage(2, 2);

    // fragment addresses (constant per thread, add stage/k offsets)
    const uint32_t a_addr0 = sbase + (warp_m + (lane & 15)) * ROWB + (lane >> 4) * 16;
    const uint32_t b_addr0 = sbase + A_ST
                           + (warp_n + ((lane >> 4) << 3) + (lane & 7)) * ROWB
                           + (((lane >> 3) & 1) << 4);

    for (int k = 0; k < NK; k++) {
        const int buf = k & 3;
        if (k < NK - 2)       { CP_WAIT(2); }
        else if (k == NK - 2) { CP_WAIT(1); }
        else                  { CP_WAIT(0); }
        __syncthreads();

        const uint32_t soff = buf * ST_BYTES;
#pragma unroll
        for (int ks = 0; ks < 2; ks++) {            // two k16 steps per chunk
            uint32_t af[4][4], bf[4][4];
#pragma unroll
            for (int mi = 0; mi < 4; mi++)
                ldsm4(af[mi], a_addr0 + soff + mi * 16 * ROWB + ks * 32);
#pragma unroll
            for (int nj = 0; nj < 4; nj++)
                ldsm4(bf[nj], b_addr0 + soff + nj * 16 * ROWB + ks * 32);
#pragma unroll
            for (int mi = 0; mi < 4; mi++) {
#pragma unroll
                for (int ni = 0; ni < 8; ni++) {
                    const uint32_t* bp = &bf[ni >> 1][(ni & 1) * 2];
                    mma16816(acc[mi][ni], af[mi], bp);
                }
            }
        }
        // no trailing barrier: iter-k writes target buf (k+3)&3 = (k-1)&3,
        // whose readers (iter k-1 ldsm) all passed this iter's top barrier.
        const int kn = k + 3;
        if (kn < NK) load_stage(kn, kn & 3);
    }

    // epilogue: bias + fp32 store (float2 per reg-pair)
#pragma unroll
    for (int mi = 0; mi < 4; mi++) {
#pragma unroll
        for (int ni = 0; ni < 8; ni++) {
            int row = m0 + warp_m + mi * 16 + (lane >> 2);
            int col = n0 + warp_n + ni * 8 + (lane & 3) * 2;
            float b0 = bias[col], b1 = bias[col + 1];
            float2 v0 = make_float2(acc[mi][ni][0] + b0, acc[mi][ni][1] + b1);
            float2 v1 = make_float2(acc[mi][ni][2] + b0, acc[mi][ni][3] + b1);
            *(float2*)(C + (size_t)row * Nout + col)       = v0;
            *(float2*)(C + (size_t)(row + 8) * Nout + col) = v1;
        }
    }
}

// ---------------------------------------------------------------------------
// Attention: one block per (b, h). 32 q x 32 k x 128 d. Ctx phase is
// dim-contiguous per thread (vectorizable LDS/STS). Output written in
// deduped bf16 A-side layout [ch | cl] (stride KTA) into g_ctxa.
// ---------------------------------------------------------------------------
__global__ __launch_bounds__(128)
void attn_kernel(const float* __restrict__ qkv,
                 const unsigned char* __restrict__ pad,
                 __nv_bfloat16* __restrict__ ctxa)
{
    __shared__ float qs[32 * 129];
    __shared__ float ks[32 * 129];
    __shared__ float vs[32 * 129];
    __shared__ float sc[32 * 33];
    __shared__ int   spad[32];

    const int b = blockIdx.x >> 2;
    const int h = blockIdx.x & 3;
    const int tid = threadIdx.x;

    const float* base = qkv + (size_t)b * N_ * QKV_COLS + h * HD_;

    for (int idx = tid; idx < N_ * HD_; idx += 128) {
        int r = idx >> 7, c = idx & 127;
        qs[r * 129 + c] = base[(size_t)r * QKV_COLS            + c];
        ks[r * 129 + c] = base[(size_t)r * QKV_COLS + D_     + c];
        vs[r * 129 + c] = base[(size_t)r * QKV_COLS + 2 * D_ + c];
    }
    if (tid < 32) spad[tid] = pad[b * N_ + tid];
    __syncthreads();

    const int q = tid >> 2;
    const int kbase = (tid & 3) * 8;
    const float* qrow = &qs[q * 129];

    float acc[8];
#pragma unroll
    for (int i = 0; i < 8; i++) acc[i] = 0.f;

    for (int c0 = 0; c0 < HD_; c0 += 16) {
        float qreg[16];
#pragma unroll
        for (int c = 0; c < 16; c++) qreg[c] = qrow[c0 + c];
#pragma unroll
        for (int i = 0; i < 8; i++) {
            const float* krow = &ks[(kbase + i) * 129 + c0];
#pragma unroll
            for (int c = 0; c < 16; c++) acc[i] += qreg[c] * krow[c];
        }
    }

    const float scale = 0.08838834764831845f;  // 1/sqrt(128)
#pragma unroll
    for (int i = 0; i < 8; i++) {
        int k = kbase + i;
        float s = (k == q || spad[k]) ? -1e30f : acc[i] * scale;
        sc[q * 33 + k] = s;
    }
    __syncthreads();

    if (tid < 32) {
        float m = -1e30f;
#pragma unroll
        for (int k = 0; k < 32; k++) m = fmaxf(m, sc[tid * 33 + k]);
        float sum = 0.f;
#pragma unroll
        for (int k = 0; k < 32; k++) {
            float e = __expf(sc[tid * 33 + k] - m);
            sc[tid * 33 + k] = e;
            sum += e;
        }
        float inv = 1.f / sum;
#pragma unroll
        for (int k = 0; k < 32; k++) sc[tid * 33 + k] *= inv;
    }
    __syncthreads();

    // ctx: thread handles q = tid/4, dims [dq*32, dq*32+32) contiguous
    {
        const int dq = tid & 3;
        float o[32];
#pragma unroll
        for (int j = 0; j < 32; j++) o[j] = 0.f;
        for (int k = 0; k < 32; k++) {
            float p = sc[q * 33 + k];
            const float* vrow = &vs[k * 129 + dq * 32];
#pragma unroll
            for (int j = 0; j < 32; j++) o[j] += p * vrow[j];
        }
        // stage into ks (done with scores; ks free after score phase)
        float* stg = &ks[q * 129 + dq * 32];
#pragma unroll
        for (int j = 0; j < 32; j++) stg[j] = o[j];
    }
    __syncthreads();

    // write deduped bf16 ctx: [ch | cl]
    __nv_bfloat16* outa = ctxa + (size_t)b * N_ * KTA + h * HD_;
    for (int idx = tid; idx < N_ * HD_; idx += 128) {
        int r = idx >> 7, c = idx & 127;
        float v = ks[r * 129 + c];
        __nv_bfloat16 hi, lo;
        split_bf16(v, hi, lo);
        __nv_bfloat16* p = outa + (size_t)r * KTA + c;
        p[0]   = hi;
        p[512] = lo;
    }
}

// ---------------------------------------------------------------------------
// Launch
// ---------------------------------------------------------------------------
extern "C" void kernel_launch(void* const* d_in, const int* in_sizes, int n_in,
                              void* d_out, int out_size)
{
    const float*         x     = (const float*)d_in[0];
    const unsigned char* pmask = (const unsigned char*)d_in[1];
    const float*         w_in  = (const float*)d_in[2];
    const float*         b_in  = (const float*)d_in[3];
    const float*         w_out = (const float*)d_in[4];
    const float*         b_out = (const float*)d_in[5];
    float*               out   = (float*)d_out;

    void *qkv_p, *xa_p, *ctxa_p, *wina_p, *wouta_p;
    cudaGetSymbolAddress(&qkv_p,   g_qkv);
    cudaGetSymbolAddress(&xa_p,    g_xa);
    cudaGetSymbolAddress(&ctxa_p,  g_ctxa);
    cudaGetSymbolAddress(&wina_p,  g_wina);
    cudaGetSymbolAddress(&wouta_p, g_wouta);
    float*         qkv   = (float*)qkv_p;
    __nv_bfloat16* xa    = (__nv_bfloat16*)xa_p;
    __nv_bfloat16* ctxa  = (__nv_bfloat16*)ctxa_p;
    __nv_bfloat16* wina  = (__nv_bfloat16*)wina_p;
    __nv_bfloat16* wouta = (__nv_bfloat16*)wouta_p;

    cudaFuncSetAttribute(gemm_mma, cudaFuncAttributeMaxDynamicSharedMemorySize,
                         GEMM_SMEM);

    // split-precision conversions
    {
        int t4 = M_ROWS * 128;
        conv_a<<<(t4 + 255) / 256, 256>>>(x, xa, t4);
    }
    {
        int t4 = QKV_COLS * 128;
        conv_b<<<(t4 + 255) / 256, 256>>>(w_in, wina, t4);
    }
    {
        int t4 = D_ * 128;
        conv_b<<<(t4 + 255) / 256, 256>>>(w_out, wouta, t4);
    }

    // 1) QKV projection: (32768 x 1536)
    {
        dim3 grid(QKV_COLS / BN, M_ROWS / BM);   // (12, 256)
        gemm_mma<<<grid, 128, GEMM_SMEM>>>(xa, wina, b_in, qkv, QKV_COLS);
    }

    // 2) attention (writes deduped bf16 ctx)
    attn_kernel<<<B_ * H_, 128>>>(qkv, pmask, ctxa);

    // 3) output projection: (32768 x 512)
    {
        dim3 grid(D_ / BN, M_ROWS / BM);         // (4, 256)
        gemm_mma<<<grid, 128, GEMM_SMEM>>>(ctxa, wouta, b_out, out, D_);
    }
}

// round 14
// speedup vs baseline: 1.2084x; 1.2084x over previous
#include <cuda_runtime.h>
#include <cuda_bf16.h>
#include <cstdint>

// Problem constants
#define B_   1024
#define N_   32
#define D_   512
#define H_   4
#define HD_  128
#define QKV_COLS 1536
#define M_ROWS   32768
#define KT   1536              // logical K (3 * 512): [Ah|Al|Ah] x [Bh|Bh|Bl]
#define KTA  1024              // A-side physical stride: [Ah|Al] (region 3 = region 1)

// GEMM tiling (round-9 proven config)
#define BM 128
#define BN 128
#define BK 32                       // bf16 per K-chunk (64B data per row)
#define STAGES 4
#define ROWB 80                     // smem row stride bytes (64 data + 16 pad)
#define A_ST (BM * ROWB)            // 10240
#define ST_BYTES (2 * A_ST)         // 20480 (A tile + B tile)
#define GEMM_SMEM (STAGES * ST_BYTES)  // 81920
#define NK (KT / BK)                // 48

// Scratch (device globals — allocation-free per harness rules)
__device__ float         g_qkv [(size_t)M_ROWS * QKV_COLS];  // fp32 (B*N,1536)
__device__ __nv_bfloat16 g_xa  [(size_t)M_ROWS * KTA];       // x  split [Ah|Al]
__device__ __nv_bfloat16 g_ctxa[(size_t)M_ROWS * KTA];       // ctx split [ch|cl]
__device__ __nv_bfloat16 g_wina[(size_t)QKV_COLS * KT];      // W_in  split [Bh|Bh|Bl]
__device__ __nv_bfloat16 g_wouta[(size_t)D_ * KT];           // W_out split [Bh|Bh|Bl]

// ---------------------------------------------------------------------------
// PTX helpers (all arch-agnostic: cp.async / ldmatrix / mma.sync)
// ---------------------------------------------------------------------------
__device__ __forceinline__ uint32_t smem_u32(const void* p) {
    uint32_t a;
    asm("{ .reg .u64 t; cvta.to.shared.u64 t, %1; cvt.u32.u64 %0, t; }"
        : "=r"(a) : "l"(p));
    return a;
}

__device__ __forceinline__ void cp_async16(uint32_t s, const void* g) {
    asm volatile("cp.async.cg.shared.global [%0], [%1], 16;"
                 :: "r"(s), "l"(g) : "memory");
}
#define CP_COMMIT() asm volatile("cp.async.commit_group;" ::: "memory")
#define CP_WAIT(n)  asm volatile("cp.async.wait_group %0;" :: "n"(n) : "memory")

__device__ __forceinline__ void ldsm4(uint32_t* r, uint32_t addr) {
    asm volatile("ldmatrix.sync.aligned.m8n8.x4.shared.b16 {%0,%1,%2,%3}, [%4];"
                 : "=r"(r[0]), "=r"(r[1]), "=r"(r[2]), "=r"(r[3]) : "r"(addr));
}

__device__ __forceinline__ void mma16816(float* d, const uint32_t* a,
                                         const uint32_t* b) {
    asm volatile("mma.sync.aligned.m16n8k16.row.col.f32.bf16.bf16.f32 "
                 "{%0,%1,%2,%3}, {%4,%5,%6,%7}, {%8,%9}, {%0,%1,%2,%3};"
                 : "+f"(d[0]), "+f"(d[1]), "+f"(d[2]), "+f"(d[3])
                 : "r"(a[0]), "r"(a[1]), "r"(a[2]), "r"(a[3]),
                   "r"(b[0]), "r"(b[1]));
}

// ---------------------------------------------------------------------------
// Split-precision conversion kernels
// ---------------------------------------------------------------------------
__device__ __forceinline__ void split_bf16(float v, __nv_bfloat16& hi, __nv_bfloat16& lo) {
    hi = __float2bfloat16_rn(v);
    lo = __float2bfloat16_rn(v - __bfloat162float(hi));
}

// A-side layout: [Ah | Al] (stride KTA)
__global__ void conv_a(const float* __restrict__ src, __nv_bfloat16* __restrict__ dst,
                       int total4) {
    int idx = blockIdx.x * 256 + threadIdx.x;
    if (idx >= total4) return;
    int row = idx >> 7;            // 128 float4 per 512-col row
    int c4  = (idx & 127) << 2;
    float4 v = *(const float4*)(src + (size_t)row * 512 + c4);
    __nv_bfloat16 h0, h1, h2, h3, l0, l1, l2, l3;
    split_bf16(v.x, h0, l0); split_bf16(v.y, h1, l1);
    split_bf16(v.z, h2, l2); split_bf16(v.w, h3, l3);
    __nv_bfloat16* d = dst + (size_t)row * KTA + c4;
    ((__nv_bfloat162*)(d       ))[0] = __nv_bfloat162(h0, h1);
    ((__nv_bfloat162*)(d       ))[1] = __nv_bfloat162(h2, h3);
    ((__nv_bfloat162*)(d +  512))[0] = __nv_bfloat162(l0, l1);
    ((__nv_bfloat162*)(d +  512))[1] = __nv_bfloat162(l2, l3);
}

// B-side layout: [Bh | Bh | Bl] (stride KT)
__global__ void conv_b(const float* __restrict__ src, __nv_bfloat16* __restrict__ dst,
                       int total4) {
    int idx = blockIdx.x * 256 + threadIdx.x;
    if (idx >= total4) return;
    int row = idx >> 7;
    int c4  = (idx & 127) << 2;
    float4 v = *(const float4*)(src + (size_t)row * 512 + c4);
    __nv_bfloat16 h0, h1, h2, h3, l0, l1, l2, l3;
    split_bf16(v.x, h0, l0); split_bf16(v.y, h1, l1);
    split_bf16(v.z, h2, l2); split_bf16(v.w, h3, l3);
    __nv_bfloat16* d = dst + (size_t)row * KT + c4;
    ((__nv_bfloat162*)(d       ))[0] = __nv_bfloat162(h0, h1);
    ((__nv_bfloat162*)(d       ))[1] = __nv_bfloat162(h2, h3);
    ((__nv_bfloat162*)(d +  512))[0] = __nv_bfloat162(h0, h1);
    ((__nv_bfloat162*)(d +  512))[1] = __nv_bfloat162(h2, h3);
    ((__nv_bfloat162*)(d + 1024))[0] = __nv_bfloat162(l0, l1);
    ((__nv_bfloat162*)(d + 1024))[1] = __nv_bfloat162(l2, l3);
}

// ---------------------------------------------------------------------------
// HMMA GEMM: C[M, Nout](fp32) = A[M, KT](bf16) @ B[Nout, KT](bf16)^T + bias
// Round-9 config: CTA 128x128, 4 warps (2x2), warp tile 64x64, K-chunk 32,
// 4-stage cp.async, 80B row stride, one barrier per K-chunk.
// A is stored deduped ([Ah|Al], stride KTA); logical chunk kc>=32 reads
// physical chunk kc-32 (region 3 == region 1). Measured neutral on GEMM time.
// ---------------------------------------------------------------------------
__global__ __launch_bounds__(128, 2)
void gemm_mma(const __nv_bfloat16* __restrict__ A,
              const __nv_bfloat16* __restrict__ Bm,
              const float* __restrict__ bias, float* __restrict__ C, int Nout)
{
    extern __shared__ __align__(128) char smem[];
    const int tid  = threadIdx.x;
    const int wid  = tid >> 5;
    const int lane = tid & 31;
    const int m0 = blockIdx.y * BM;
    const int n0 = blockIdx.x * BN;
    const int warp_m = (wid >> 1) * 64;   // 0 or 64
    const int warp_n = (wid & 1) * 64;    // 0 or 64
    const uint32_t sbase = smem_u32(smem);

    // load thread mapping: 512 16B-chunks per tile, 4 per thread per tile
    const int lr = tid >> 2;        // 0..31 base row
    const int lc = tid & 3;         // 16B chunk in row

    float acc[4][8][4];
#pragma unroll
    for (int mi = 0; mi < 4; mi++)
#pragma unroll
        for (int ni = 0; ni < 8; ni++)
#pragma unroll
            for (int r = 0; r < 4; r++) acc[mi][ni][r] = 0.f;

    auto load_stage = [&](int kc, int buf) {
        const uint32_t as = sbase + buf * ST_BYTES;
        const uint32_t bs = as + A_ST;
        const int kca = (kc < 32) ? kc : kc - 32;   // A region-3 dedup remap
        const __nv_bfloat16* Ag = A  + (size_t)m0 * KTA + kca * BK;
        const __nv_bfloat16* Bg = Bm + (size_t)n0 * KT  + kc  * BK;
#pragma unroll
        for (int i = 0; i < 4; i++) {
            int r = lr + i * 32;
            cp_async16(as + r * ROWB + lc * 16, Ag + (size_t)r * KTA + lc * 8);
        }
#pragma unroll
        for (int i = 0; i < 4; i++) {
            int r = lr + i * 32;
            cp_async16(bs + r * ROWB + lc * 16, Bg + (size_t)r * KT + lc * 8);
        }
        CP_COMMIT();
    };

    load_stage(0, 0);
    load_stage(1, 1);
    load_stage(2, 2);

    // fragment addresses (constant per thread, add stage/k offsets)
    const uint32_t a_addr0 = sbase + (warp_m + (lane & 15)) * ROWB + (lane >> 4) * 16;
    const uint32_t b_addr0 = sbase + A_ST
                           + (warp_n + ((lane >> 4) << 3) + (lane & 7)) * ROWB
                           + (((lane >> 3) & 1) << 4);

    for (int k = 0; k < NK; k++) {
        const int buf = k & 3;
        if (k < NK - 2)       { CP_WAIT(2); }
        else if (k == NK - 2) { CP_WAIT(1); }
        else                  { CP_WAIT(0); }
        __syncthreads();

        const uint32_t soff = buf * ST_BYTES;
#pragma unroll
        for (int ks = 0; ks < 2; ks++) {            // two k16 steps per chunk
            uint32_t af[4][4], bf[4][4];
#pragma unroll
            for (int mi = 0; mi < 4; mi++)
                ldsm4(af[mi], a_addr0 + soff + mi * 16 * ROWB + ks * 32);
#pragma unroll
            for (int nj = 0; nj < 4; nj++)
                ldsm4(bf[nj], b_addr0 + soff + nj * 16 * ROWB + ks * 32);
#pragma unroll
            for (int mi = 0; mi < 4; mi++) {
#pragma unroll
                for (int ni = 0; ni < 8; ni++) {
                    const uint32_t* bp = &bf[ni >> 1][(ni & 1) * 2];
                    mma16816(acc[mi][ni], af[mi], bp);
                }
            }
        }
        // no trailing barrier: iter-k writes target buf (k+3)&3 = (k-1)&3,
        // whose readers (iter k-1 ldsm) all passed this iter's top barrier.
        const int kn = k + 3;
        if (kn < NK) load_stage(kn, kn & 3);
    }

    // epilogue: bias + fp32 store (float2 per reg-pair)
#pragma unroll
    for (int mi = 0; mi < 4; mi++) {
#pragma unroll
        for (int ni = 0; ni < 8; ni++) {
            int row = m0 + warp_m + mi * 16 + (lane >> 2);
            int col = n0 + warp_n + ni * 8 + (lane & 3) * 2;
            float b0 = bias[col], b1 = bias[col + 1];
            float2 v0 = make_float2(acc[mi][ni][0] + b0, acc[mi][ni][1] + b1);
            float2 v1 = make_float2(acc[mi][ni][2] + b0, acc[mi][ni][3] + b1);
            *(float2*)(C + (size_t)row * Nout + col)       = v0;
            *(float2*)(C + (size_t)(row + 8) * Nout + col) = v1;
        }
    }
}

// ---------------------------------------------------------------------------
// Attention: one block per (b, h). 32 q x 32 k x 128 d. Ctx phase uses the
// round-9 stride-4 dim interleave (dq + 4*j) — conflict-free on the smem
// banks (the round-13 contiguous variant was a 4-way conflict). Output is
// the deduped bf16 A-side layout [ch | cl] (stride KTA).
// ---------------------------------------------------------------------------
__global__ __launch_bounds__(128)
void attn_kernel(const float* __restrict__ qkv,
                 const unsigned char* __restrict__ pad,
                 __nv_bfloat16* __restrict__ ctxa)
{
    __shared__ float qs[32 * 129];
    __shared__ float ks[32 * 129];
    __shared__ float vs[32 * 129];
    __shared__ float sc[32 * 33];
    __shared__ int   spad[32];

    const int b = blockIdx.x >> 2;
    const int h = blockIdx.x & 3;
    const int tid = threadIdx.x;

    const float* base = qkv + (size_t)b * N_ * QKV_COLS + h * HD_;

    for (int idx = tid; idx < N_ * HD_; idx += 128) {
        int r = idx >> 7, c = idx & 127;
        qs[r * 129 + c] = base[(size_t)r * QKV_COLS            + c];
        ks[r * 129 + c] = base[(size_t)r * QKV_COLS + D_     + c];
        vs[r * 129 + c] = base[(size_t)r * QKV_COLS + 2 * D_ + c];
    }
    if (tid < 32) spad[tid] = pad[b * N_ + tid];
    __syncthreads();

    const int q = tid >> 2;
    const int kbase = (tid & 3) * 8;
    const float* qrow = &qs[q * 129];

    float acc[8];
#pragma unroll
    for (int i = 0; i < 8; i++) acc[i] = 0.f;

    for (int c0 = 0; c0 < HD_; c0 += 16) {
        float qreg[16];
#pragma unroll
        for (int c = 0; c < 16; c++) qreg[c] = qrow[c0 + c];
#pragma unroll
        for (int i = 0; i < 8; i++) {
            const float* krow = &ks[(kbase + i) * 129 + c0];
#pragma unroll
            for (int c = 0; c < 16; c++) acc[i] += qreg[c] * krow[c];
        }
    }

    const float scale = 0.08838834764831845f;  // 1/sqrt(128)
#pragma unroll
    for (int i = 0; i < 8; i++) {
        int k = kbase + i;
        float s = (k == q || spad[k]) ? -1e30f : acc[i] * scale;
        sc[q * 33 + k] = s;
    }
    __syncthreads();

    if (tid < 32) {
        float m = -1e30f;
#pragma unroll
        for (int k = 0; k < 32; k++) m = fmaxf(m, sc[tid * 33 + k]);
        float sum = 0.f;
#pragma unroll
        for (int k = 0; k < 32; k++) {
            float e = __expf(sc[tid * 33 + k] - m);
            sc[tid * 33 + k] = e;
            sum += e;
        }
        float inv = 1.f / sum;
#pragma unroll
        for (int k = 0; k < 32; k++) sc[tid * 33 + k] *= inv;
    }
    __syncthreads();

    // ctx: thread handles q = tid/4, dims d = (tid&3) + 4*j (bank-friendly)
    {
        const int dq = tid & 3;
        float o[32];
#pragma unroll
        for (int j = 0; j < 32; j++) o[j] = 0.f;
        for (int k = 0; k < 32; k++) {
            float p = sc[q * 33 + k];
            const float* vrow = &vs[k * 129 + dq];
#pragma unroll
            for (int j = 0; j < 32; j++) o[j] += p * vrow[4 * j];
        }
        // stage into ks (done with scores; ks free after score phase)
        float* stg = &ks[q * 129 + dq];
#pragma unroll
        for (int j = 0; j < 32; j++) stg[4 * j] = o[j];
    }
    __syncthreads();

    // write deduped bf16 ctx: [ch | cl]
    __nv_bfloat16* outa = ctxa + (size_t)b * N_ * KTA + h * HD_;
    for (int idx = tid; idx < N_ * HD_; idx += 128) {
        int r = idx >> 7, c = idx & 127;
        float v = ks[r * 129 + c];
        __nv_bfloat16 hi, lo;
        split_bf16(v, hi, lo);
        __nv_bfloat16* p = outa + (size_t)r * KTA + c;
        p[0]   = hi;
        p[512] = lo;
    }
}

// ---------------------------------------------------------------------------
// Launch
// ---------------------------------------------------------------------------
extern "C" void kernel_launch(void* const* d_in, const int* in_sizes, int n_in,
                              void* d_out, int out_size)
{
    const float*         x     = (const float*)d_in[0];
    const unsigned char* pmask = (const unsigned char*)d_in[1];
    const float*         w_in  = (const float*)d_in[2];
    const float*         b_in  = (const float*)d_in[3];
    const float*         w_out = (const float*)d_in[4];
    const float*         b_out = (const float*)d_in[5];
    float*               out   = (float*)d_out;

    void *qkv_p, *xa_p, *ctxa_p, *wina_p, *wouta_p;
    cudaGetSymbolAddress(&qkv_p,   g_qkv);
    cudaGetSymbolAddress(&xa_p,    g_xa);
    cudaGetSymbolAddress(&ctxa_p,  g_ctxa);
    cudaGetSymbolAddress(&wina_p,  g_wina);
    cudaGetSymbolAddress(&wouta_p, g_wouta);
    float*         qkv   = (float*)qkv_p;
    __nv_bfloat16* xa    = (__nv_bfloat16*)xa_p;
    __nv_bfloat16* ctxa  = (__nv_bfloat16*)ctxa_p;
    __nv_bfloat16* wina  = (__nv_bfloat16*)wina_p;
    __nv_bfloat16* wouta = (__nv_bfloat16*)wouta_p;

    cudaFuncSetAttribute(gemm_mma, cudaFuncAttributeMaxDynamicSharedMemorySize,
                         GEMM_SMEM);

    // split-precision conversions
    {
        int t4 = M_ROWS * 128;
        conv_a<<<(t4 + 255) / 256, 256>>>(x, xa, t4);
    }
    {
        int t4 = QKV_COLS * 128;
        conv_b<<<(t4 + 255) / 256, 256>>>(w_in, wina, t4);
    }
    {
        int t4 = D_ * 128;
        conv_b<<<(t4 + 255) / 256, 256>>>(w_out, wouta, t4);
    }

    // 1) QKV projection: (32768 x 1536)
    {
        dim3 grid(QKV_COLS / BN, M_ROWS / BM);   // (12, 256)
        gemm_mma<<<grid, 128, GEMM_SMEM>>>(xa, wina, b_in, qkv, QKV_COLS);
    }

    // 2) attention (writes deduped bf16 ctx)
    attn_kernel<<<B_ * H_, 128>>>(qkv, pmask, ctxa);

    // 3) output projection: (32768 x 512)
    {
        dim3 grid(D_ / BN, M_ROWS / BM);         // (4, 256)
        gemm_mma<<<grid, 128, GEMM_SMEM>>>(ctxa, wouta, b_out, out, D_);
    }
}

// round 15
// speedup vs baseline: 1.2280x; 1.0162x over previous
#include <cuda_runtime.h>
#include <cuda_bf16.h>
#include <cstdint>

// Problem constants
#define B_   1024
#define N_   32
#define D_   512
#define H_   4
#define HD_  128
#define QKV_COLS 1536
#define M_ROWS   32768
#define KT   1536              // logical K (3 * 512): [Ah|Al|Ah] x [Bh|Bh|Bl]
#define KTA  1024              // A-side physical stride: [Ah|Al] (region 3 = region 1)

// GEMM tiling (round-9 proven config)
#define BM 128
#define BN 128
#define BK 32                       // bf16 per K-chunk (64B data per row)
#define STAGES 4
#define ROWB 80                     // smem row stride bytes (64 data + 16 pad)
#define A_ST (BM * ROWB)            // 10240
#define ST_BYTES (2 * A_ST)         // 20480 (A tile + B tile)
#define GEMM_SMEM (STAGES * ST_BYTES)  // 81920
#define NK (KT / BK)                // 48

// Scratch (device globals — allocation-free per harness rules)
__device__ float         g_qkv [(size_t)M_ROWS * QKV_COLS];  // fp32 (B*N,1536)
__device__ __nv_bfloat16 g_xa  [(size_t)M_ROWS * KTA];       // x  split [Ah|Al]
__device__ __nv_bfloat16 g_ctxa[(size_t)M_ROWS * KTA];       // ctx split [ch|cl]
__device__ __nv_bfloat16 g_wina[(size_t)QKV_COLS * KT];      // W_in  split [Bh|Bh|Bl]
__device__ __nv_bfloat16 g_wouta[(size_t)D_ * KT];           // W_out split [Bh|Bh|Bl]

// ---------------------------------------------------------------------------
// PTX helpers (all arch-agnostic: cp.async / ldmatrix / mma.sync)
// ---------------------------------------------------------------------------
__device__ __forceinline__ uint32_t smem_u32(const void* p) {
    uint32_t a;
    asm("{ .reg .u64 t; cvta.to.shared.u64 t, %1; cvt.u32.u64 %0, t; }"
        : "=r"(a) : "l"(p));
    return a;
}

__device__ __forceinline__ void cp_async16(uint32_t s, const void* g) {
    asm volatile("cp.async.cg.shared.global [%0], [%1], 16;"
                 :: "r"(s), "l"(g) : "memory");
}
#define CP_COMMIT() asm volatile("cp.async.commit_group;" ::: "memory")
#define CP_WAIT(n)  asm volatile("cp.async.wait_group %0;" :: "n"(n) : "memory")

__device__ __forceinline__ void ldsm4(uint32_t* r, uint32_t addr) {
    asm volatile("ldmatrix.sync.aligned.m8n8.x4.shared.b16 {%0,%1,%2,%3}, [%4];"
                 : "=r"(r[0]), "=r"(r[1]), "=r"(r[2]), "=r"(r[3]) : "r"(addr));
}

__device__ __forceinline__ void mma16816(float* d, const uint32_t* a,
                                         const uint32_t* b) {
    asm volatile("mma.sync.aligned.m16n8k16.row.col.f32.bf16.bf16.f32 "
                 "{%0,%1,%2,%3}, {%4,%5,%6,%7}, {%8,%9}, {%0,%1,%2,%3};"
                 : "+f"(d[0]), "+f"(d[1]), "+f"(d[2]), "+f"(d[3])
                 : "r"(a[0]), "r"(a[1]), "r"(a[2]), "r"(a[3]),
                   "r"(b[0]), "r"(b[1]));
}

// ---------------------------------------------------------------------------
// Split-precision conversion kernels
// ---------------------------------------------------------------------------
__device__ __forceinline__ void split_bf16(float v, __nv_bfloat16& hi, __nv_bfloat16& lo) {
    hi = __float2bfloat16_rn(v);
    lo = __float2bfloat16_rn(v - __bfloat162float(hi));
}

// A-side layout: [Ah | Al] (stride KTA)
__global__ void conv_a(const float* __restrict__ src, __nv_bfloat16* __restrict__ dst,
                       int total4) {
    int idx = blockIdx.x * 256 + threadIdx.x;
    if (idx >= total4) return;
    int row = idx >> 7;            // 128 float4 per 512-col row
    int c4  = (idx & 127) << 2;
    float4 v = *(const float4*)(src + (size_t)row * 512 + c4);
    __nv_bfloat16 h0, h1, h2, h3, l0, l1, l2, l3;
    split_bf16(v.x, h0, l0); split_bf16(v.y, h1, l1);
    split_bf16(v.z, h2, l2); split_bf16(v.w, h3, l3);
    __nv_bfloat16* d = dst + (size_t)row * KTA + c4;
    ((__nv_bfloat162*)(d       ))[0] = __nv_bfloat162(h0, h1);
    ((__nv_bfloat162*)(d       ))[1] = __nv_bfloat162(h2, h3);
    ((__nv_bfloat162*)(d +  512))[0] = __nv_bfloat162(l0, l1);
    ((__nv_bfloat162*)(d +  512))[1] = __nv_bfloat162(l2, l3);
}

// B-side layout: [Bh | Bh | Bl] (stride KT)
__global__ void conv_b(const float* __restrict__ src, __nv_bfloat16* __restrict__ dst,
                       int total4) {
    int idx = blockIdx.x * 256 + threadIdx.x;
    if (idx >= total4) return;
    int row = idx >> 7;
    int c4  = (idx & 127) << 2;
    float4 v = *(const float4*)(src + (size_t)row * 512 + c4);
    __nv_bfloat16 h0, h1, h2, h3, l0, l1, l2, l3;
    split_bf16(v.x, h0, l0); split_bf16(v.y, h1, l1);
    split_bf16(v.z, h2, l2); split_bf16(v.w, h3, l3);
    __nv_bfloat16* d = dst + (size_t)row * KT + c4;
    ((__nv_bfloat162*)(d       ))[0] = __nv_bfloat162(h0, h1);
    ((__nv_bfloat162*)(d       ))[1] = __nv_bfloat162(h2, h3);
    ((__nv_bfloat162*)(d +  512))[0] = __nv_bfloat162(h0, h1);
    ((__nv_bfloat162*)(d +  512))[1] = __nv_bfloat162(h2, h3);
    ((__nv_bfloat162*)(d + 1024))[0] = __nv_bfloat162(l0, l1);
    ((__nv_bfloat162*)(d + 1024))[1] = __nv_bfloat162(l2, l3);
}

// ---------------------------------------------------------------------------
// HMMA GEMM: C[M, Nout](fp32) = A[M, KT](bf16) @ B[Nout, KT](bf16)^T + bias
// Round-9 config: CTA 128x128, 4 warps (2x2), warp tile 64x64, K-chunk 32,
// 4-stage cp.async, 80B row stride, one barrier per K-chunk.
// A is stored deduped ([Ah|Al], stride KTA); logical chunk kc>=32 reads
// physical chunk kc-32 (region 3 == region 1). Measured neutral on GEMM time.
// ---------------------------------------------------------------------------
__global__ __launch_bounds__(128, 2)
void gemm_mma(const __nv_bfloat16* __restrict__ A,
              const __nv_bfloat16* __restrict__ Bm,
              const float* __restrict__ bias, float* __restrict__ C, int Nout)
{
    extern __shared__ __align__(128) char smem[];
    const int tid  = threadIdx.x;
    const int wid  = tid >> 5;
    const int lane = tid & 31;
    const int m0 = blockIdx.y * BM;
    const int n0 = blockIdx.x * BN;
    const int warp_m = (wid >> 1) * 64;   // 0 or 64
    const int warp_n = (wid & 1) * 64;    // 0 or 64
    const uint32_t sbase = smem_u32(smem);

    // load thread mapping: 512 16B-chunks per tile, 4 per thread per tile
    const int lr = tid >> 2;        // 0..31 base row
    const int lc = tid & 3;         // 16B chunk in row

    float acc[4][8][4];
#pragma unroll
    for (int mi = 0; mi < 4; mi++)
#pragma unroll
        for (int ni = 0; ni < 8; ni++)
#pragma unroll
            for (int r = 0; r < 4; r++) acc[mi][ni][r] = 0.f;

    auto load_stage = [&](int kc, int buf) {
        const uint32_t as = sbase + buf * ST_BYTES;
        const uint32_t bs = as + A_ST;
        const int kca = (kc < 32) ? kc : kc - 32;   // A region-3 dedup remap
        const __nv_bfloat16* Ag = A  + (size_t)m0 * KTA + kca * BK;
        const __nv_bfloat16* Bg = Bm + (size_t)n0 * KT  + kc  * BK;
#pragma unroll
        for (int i = 0; i < 4; i++) {
            int r = lr + i * 32;
            cp_async16(as + r * ROWB + lc * 16, Ag + (size_t)r * KTA + lc * 8);
        }
#pragma unroll
        for (int i = 0; i < 4; i++) {
            int r = lr + i * 32;
            cp_async16(bs + r * ROWB + lc * 16, Bg + (size_t)r * KT + lc * 8);
        }
        CP_COMMIT();
    };

    load_stage(0, 0);
    load_stage(1, 1);
    load_stage(2, 2);

    // fragment addresses (constant per thread, add stage/k offsets)
    const uint32_t a_addr0 = sbase + (warp_m + (lane & 15)) * ROWB + (lane >> 4) * 16;
    const uint32_t b_addr0 = sbase + A_ST
                           + (warp_n + ((lane >> 4) << 3) + (lane & 7)) * ROWB
                           + (((lane >> 3) & 1) << 4);

    for (int k = 0; k < NK; k++) {
        const int buf = k & 3;
        if (k < NK - 2)       { CP_WAIT(2); }
        else if (k == NK - 2) { CP_WAIT(1); }
        else                  { CP_WAIT(0); }
        __syncthreads();

        const uint32_t soff = buf * ST_BYTES;
#pragma unroll
        for (int ks = 0; ks < 2; ks++) {            // two k16 steps per chunk
            uint32_t af[4][4], bf[4][4];
#pragma unroll
            for (int mi = 0; mi < 4; mi++)
                ldsm4(af[mi], a_addr0 + soff + mi * 16 * ROWB + ks * 32);
#pragma unroll
            for (int nj = 0; nj < 4; nj++)
                ldsm4(bf[nj], b_addr0 + soff + nj * 16 * ROWB + ks * 32);
#pragma unroll
            for (int mi = 0; mi < 4; mi++) {
#pragma unroll
                for (int ni = 0; ni < 8; ni++) {
                    const uint32_t* bp = &bf[ni >> 1][(ni & 1) * 2];
                    mma16816(acc[mi][ni], af[mi], bp);
                }
            }
        }
        // no trailing barrier: iter-k writes target buf (k+3)&3 = (k-1)&3,
        // whose readers (iter k-1 ldsm) all passed this iter's top barrier.
        const int kn = k + 3;
        if (kn < NK) load_stage(kn, kn & 3);
    }

    // epilogue: bias + fp32 store (float2 per reg-pair)
#pragma unroll
    for (int mi = 0; mi < 4; mi++) {
#pragma unroll
        for (int ni = 0; ni < 8; ni++) {
            int row = m0 + warp_m + mi * 16 + (lane >> 2);
            int col = n0 + warp_n + ni * 8 + (lane & 3) * 2;
            float b0 = bias[col], b1 = bias[col + 1];
            float2 v0 = make_float2(acc[mi][ni][0] + b0, acc[mi][ni][1] + b1);
            float2 v1 = make_float2(acc[mi][ni][2] + b0, acc[mi][ni][3] + b1);
            *(float2*)(C + (size_t)row * Nout + col)       = v0;
            *(float2*)(C + (size_t)(row + 8) * Nout + col) = v1;
        }
    }
}

// ---------------------------------------------------------------------------
// Attention: one block per (b, h). 32 q x 32 k x 128 d.
// float4 smem accesses throughout:
//   - row stride 132 floats (16B-aligned rows; adjacent rows shift 4 banks)
//   - score: thread (q,dq) owns keys k = dq+4i -> the 4 dq-lanes read 4
//     ADJACENT rows = distinct bank chunks (conflict-free LDS.128)
//   - ctx: thread owns dim-chunks (dq+4jj)*4; all lanes read the same k row,
//     dq picks distinct 16B chunks (broadcast + conflict-free)
//   - no smem staging: each thread splits its 32 dims and writes bf16
//     [ch|cl] (stride KTA) directly
// Per-(q,k) and per-dim fp32 accumulation order identical to round 14.
// ---------------------------------------------------------------------------
#define AROW 132
#define SROW 36
__global__ __launch_bounds__(128)
void attn_kernel(const float* __restrict__ qkv,
                 const unsigned char* __restrict__ pad,
                 __nv_bfloat16* __restrict__ ctxa)
{
    __shared__ float qs[32 * AROW];
    __shared__ float ks[32 * AROW];
    __shared__ float vs[32 * AROW];
    __shared__ float sc[32 * SROW];
    __shared__ int   spad[32];

    const int b = blockIdx.x >> 2;
    const int h = blockIdx.x & 3;
    const int tid = threadIdx.x;

    const float* base = qkv + (size_t)b * N_ * QKV_COLS + h * HD_;

    // float4 gmem -> smem staging (8 float4 per thread per array)
    for (int u = tid; u < 32 * 32; u += 128) {
        int r  = u >> 5;
        int c4 = (u & 31) << 2;
        const float* brow = base + (size_t)r * QKV_COLS + c4;
        *(float4*)&qs[r * AROW + c4] = *(const float4*)(brow);
        *(float4*)&ks[r * AROW + c4] = *(const float4*)(brow + D_);
        *(float4*)&vs[r * AROW + c4] = *(const float4*)(brow + 2 * D_);
    }
    if (tid < 32) spad[tid] = pad[b * N_ + tid];
    __syncthreads();

    const int q  = tid >> 2;
    const int dq = tid & 3;

    // scores: thread handles keys k = dq + 4*i, i = 0..7
    float acc[8];
#pragma unroll
    for (int i = 0; i < 8; i++) acc[i] = 0.f;

    for (int c0 = 0; c0 < HD_; c0 += 16) {
        float4 qv[4];
#pragma unroll
        for (int c = 0; c < 4; c++)
            qv[c] = *(const float4*)&qs[q * AROW + c0 + 4 * c];
#pragma unroll
        for (int i = 0; i < 8; i++) {
            const float* kr = &ks[(dq + 4 * i) * AROW + c0];
#pragma unroll
            for (int c = 0; c < 4; c++) {
                float4 kv = *(const float4*)&kr[4 * c];
                acc[i] += qv[c].x * kv.x;
                acc[i] += qv[c].y * kv.y;
                acc[i] += qv[c].z * kv.z;
                acc[i] += qv[c].w * kv.w;
            }
        }
    }

    const float scale = 0.08838834764831845f;  // 1/sqrt(128)
#pragma unroll
    for (int i = 0; i < 8; i++) {
        int k = dq + 4 * i;
        float s = (k == q || spad[k]) ? -1e30f : acc[i] * scale;
        sc[q * SROW + k] = s;
    }
    __syncthreads();

    if (tid < 32) {
        float m = -1e30f;
#pragma unroll
        for (int k = 0; k < 32; k++) m = fmaxf(m, sc[tid * SROW + k]);
        float sum = 0.f;
#pragma unroll
        for (int k = 0; k < 32; k++) {
            float e = __expf(sc[tid * SROW + k] - m);
            sc[tid * SROW + k] = e;
            sum += e;
        }
        float inv = 1.f / sum;
#pragma unroll
        for (int k = 0; k < 32; k++) sc[tid * SROW + k] *= inv;
    }
    __syncthreads();

    // ctx: thread (q,dq) owns dim chunks (dq + 4*jj)*4, jj = 0..7
    float4 o[8];
#pragma unroll
    for (int jj = 0; jj < 8; jj++) o[jj] = make_float4(0.f, 0.f, 0.f, 0.f);

    for (int k = 0; k < 32; k++) {
        float p = sc[q * SROW + k];
        const float* vr = &vs[k * AROW];
#pragma unroll
        for (int jj = 0; jj < 8; jj++) {
            float4 vv = *(const float4*)&vr[(dq + 4 * jj) * 4];
            o[jj].x += p * vv.x;
            o[jj].y += p * vv.y;
            o[jj].z += p * vv.z;
            o[jj].w += p * vv.w;
        }
    }

    // direct bf16 write: [ch | cl] (stride KTA), row q, chunks (dq+4jj)*4
    __nv_bfloat16* outr = ctxa + (size_t)b * N_ * KTA + h * HD_ + (size_t)q * KTA;
#pragma unroll
    for (int jj = 0; jj < 8; jj++) {
        int d0 = (dq + 4 * jj) * 4;
        __nv_bfloat16 h0, h1, h2, h3, l0, l1, l2, l3;
        split_bf16(o[jj].x, h0, l0);
        split_bf16(o[jj].y, h1, l1);
        split_bf16(o[jj].z, h2, l2);
        split_bf16(o[jj].w, h3, l3);
        ((__nv_bfloat162*)(outr + d0))[0]       = __nv_bfloat162(h0, h1);
        ((__nv_bfloat162*)(outr + d0))[1]       = __nv_bfloat162(h2, h3);
        ((__nv_bfloat162*)(outr + 512 + d0))[0] = __nv_bfloat162(l0, l1);
        ((__nv_bfloat162*)(outr + 512 + d0))[1] = __nv_bfloat162(l2, l3);
    }
}

// ---------------------------------------------------------------------------
// Launch
// ---------------------------------------------------------------------------
extern "C" void kernel_launch(void* const* d_in, const int* in_sizes, int n_in,
                              void* d_out, int out_size)
{
    const float*         x     = (const float*)d_in[0];
    const unsigned char* pmask = (const unsigned char*)d_in[1];
    const float*         w_in  = (const float*)d_in[2];
    const float*         b_in  = (const float*)d_in[3];
    const float*         w_out = (const float*)d_in[4];
    const float*         b_out = (const float*)d_in[5];
    float*               out   = (float*)d_out;

    void *qkv_p, *xa_p, *ctxa_p, *wina_p, *wouta_p;
    cudaGetSymbolAddress(&qkv_p,   g_qkv);
    cudaGetSymbolAddress(&xa_p,    g_xa);
    cudaGetSymbolAddress(&ctxa_p,  g_ctxa);
    cudaGetSymbolAddress(&wina_p,  g_wina);
    cudaGetSymbolAddress(&wouta_p, g_wouta);
    float*         qkv   = (float*)qkv_p;
    __nv_bfloat16* xa    = (__nv_bfloat16*)xa_p;
    __nv_bfloat16* ctxa  = (__nv_bfloat16*)ctxa_p;
    __nv_bfloat16* wina  = (__nv_bfloat16*)wina_p;
    __nv_bfloat16* wouta = (__nv_bfloat16*)wouta_p;

    cudaFuncSetAttribute(gemm_mma, cudaFuncAttributeMaxDynamicSharedMemorySize,
                         GEMM_SMEM);

    // split-precision conversions
    {
        int t4 = M_ROWS * 128;
        conv_a<<<(t4 + 255) / 256, 256>>>(x, xa, t4);
    }
    {
        int t4 = QKV_COLS * 128;
        conv_b<<<(t4 + 255) / 256, 256>>>(w_in, wina, t4);
    }
    {
        int t4 = D_ * 128;
        conv_b<<<(t4 + 255) / 256, 256>>>(w_out, wouta, t4);
    }

    // 1) QKV projection: (32768 x 1536)
    {
        dim3 grid(QKV_COLS / BN, M_ROWS / BM);   // (12, 256)
        gemm_mma<<<grid, 128, GEMM_SMEM>>>(xa, wina, b_in, qkv, QKV_COLS);
    }

    // 2) attention (writes deduped bf16 ctx)
    attn_kernel<<<B_ * H_, 128>>>(qkv, pmask, ctxa);

    // 3) output projection: (32768 x 512)
    {
        dim3 grid(D_ / BN, M_ROWS / BM);         // (4, 256)
        gemm_mma<<<grid, 128, GEMM_SMEM>>>(ctxa, wouta, b_out, out, D_);
    }
}

// round 16
// speedup vs baseline: 1.2544x; 1.0215x over previous
#include <cuda_runtime.h>
#include <cuda_bf16.h>
#include <cstdint>

// Problem constants
#define B_   1024
#define N_   32
#define D_   512
#define H_   4
#define HD_  128
#define QKV_COLS 1536
#define M_ROWS   32768
#define KT   1536              // logical K (3 * 512): [Ah|Al|Ah] x [Bh|Bh|Bl]
#define KTA  1024              // A-side physical stride: [Ah|Al] (region 3 = region 1)

// GEMM tiling (round-9 proven config)
#define BM 128
#define BN 128
#define BK 32                       // bf16 per K-chunk (64B data per row)
#define STAGES 4
#define ROWB 80                     // smem row stride bytes (64 data + 16 pad)
#define A_ST (BM * ROWB)            // 10240
#define ST_BYTES (2 * A_ST)         // 20480 (A tile + B tile)
#define GEMM_SMEM (STAGES * ST_BYTES)  // 81920
#define NK (KT / BK)                // 48

// Scratch (device globals — allocation-free per harness rules)
__device__ float         g_qkv [(size_t)M_ROWS * QKV_COLS];  // fp32 (B*N,1536)
__device__ __nv_bfloat16 g_xa  [(size_t)M_ROWS * KTA];       // x  split [Ah|Al]
__device__ __nv_bfloat16 g_ctxa[(size_t)M_ROWS * KTA];       // ctx split [ch|cl]
__device__ __nv_bfloat16 g_wina[(size_t)QKV_COLS * KT];      // W_in  split [Bh|Bh|Bl]
__device__ __nv_bfloat16 g_wouta[(size_t)D_ * KT];           // W_out split [Bh|Bh|Bl]

// ---------------------------------------------------------------------------
// PTX helpers (all arch-agnostic: cp.async / ldmatrix / mma.sync)
// ---------------------------------------------------------------------------
__device__ __forceinline__ uint32_t smem_u32(const void* p) {
    uint32_t a;
    asm("{ .reg .u64 t; cvta.to.shared.u64 t, %1; cvt.u32.u64 %0, t; }"
        : "=r"(a) : "l"(p));
    return a;
}

__device__ __forceinline__ void cp_async16(uint32_t s, const void* g) {
    asm volatile("cp.async.cg.shared.global [%0], [%1], 16;"
                 :: "r"(s), "l"(g) : "memory");
}
#define CP_COMMIT() asm volatile("cp.async.commit_group;" ::: "memory")
#define CP_WAIT(n)  asm volatile("cp.async.wait_group %0;" :: "n"(n) : "memory")

__device__ __forceinline__ void ldsm4(uint32_t* r, uint32_t addr) {
    asm volatile("ldmatrix.sync.aligned.m8n8.x4.shared.b16 {%0,%1,%2,%3}, [%4];"
                 : "=r"(r[0]), "=r"(r[1]), "=r"(r[2]), "=r"(r[3]) : "r"(addr));
}

__device__ __forceinline__ void mma16816(float* d, const uint32_t* a,
                                         const uint32_t* b) {
    asm volatile("mma.sync.aligned.m16n8k16.row.col.f32.bf16.bf16.f32 "
                 "{%0,%1,%2,%3}, {%4,%5,%6,%7}, {%8,%9}, {%0,%1,%2,%3};"
                 : "+f"(d[0]), "+f"(d[1]), "+f"(d[2]), "+f"(d[3])
                 : "r"(a[0]), "r"(a[1]), "r"(a[2]), "r"(a[3]),
                   "r"(b[0]), "r"(b[1]));
}

// ---------------------------------------------------------------------------
// Split-precision conversion kernels
// ---------------------------------------------------------------------------
__device__ __forceinline__ void split_bf16(float v, __nv_bfloat16& hi, __nv_bfloat16& lo) {
    hi = __float2bfloat16_rn(v);
    lo = __float2bfloat16_rn(v - __bfloat162float(hi));
}

// A-side layout: [Ah | Al] (stride KTA)
__global__ void conv_a(const float* __restrict__ src, __nv_bfloat16* __restrict__ dst,
                       int total4) {
    int idx = blockIdx.x * 256 + threadIdx.x;
    if (idx >= total4) return;
    int row = idx >> 7;            // 128 float4 per 512-col row
    int c4  = (idx & 127) << 2;
    float4 v = *(const float4*)(src + (size_t)row * 512 + c4);
    __nv_bfloat16 h0, h1, h2, h3, l0, l1, l2, l3;
    split_bf16(v.x, h0, l0); split_bf16(v.y, h1, l1);
    split_bf16(v.z, h2, l2); split_bf16(v.w, h3, l3);
    __nv_bfloat16* d = dst + (size_t)row * KTA + c4;
    ((__nv_bfloat162*)(d       ))[0] = __nv_bfloat162(h0, h1);
    ((__nv_bfloat162*)(d       ))[1] = __nv_bfloat162(h2, h3);
    ((__nv_bfloat162*)(d +  512))[0] = __nv_bfloat162(l0, l1);
    ((__nv_bfloat162*)(d +  512))[1] = __nv_bfloat162(l2, l3);
}

// B-side layout: [Bh | Bh | Bl] (stride KT)
__global__ void conv_b(const float* __restrict__ src, __nv_bfloat16* __restrict__ dst,
                       int total4) {
    int idx = blockIdx.x * 256 + threadIdx.x;
    if (idx >= total4) return;
    int row = idx >> 7;
    int c4  = (idx & 127) << 2;
    float4 v = *(const float4*)(src + (size_t)row * 512 + c4);
    __nv_bfloat16 h0, h1, h2, h3, l0, l1, l2, l3;
    split_bf16(v.x, h0, l0); split_bf16(v.y, h1, l1);
    split_bf16(v.z, h2, l2); split_bf16(v.w, h3, l3);
    __nv_bfloat16* d = dst + (size_t)row * KT + c4;
    ((__nv_bfloat162*)(d       ))[0] = __nv_bfloat162(h0, h1);
    ((__nv_bfloat162*)(d       ))[1] = __nv_bfloat162(h2, h3);
    ((__nv_bfloat162*)(d +  512))[0] = __nv_bfloat162(h0, h1);
    ((__nv_bfloat162*)(d +  512))[1] = __nv_bfloat162(h2, h3);
    ((__nv_bfloat162*)(d + 1024))[0] = __nv_bfloat162(l0, l1);
    ((__nv_bfloat162*)(d + 1024))[1] = __nv_bfloat162(l2, l3);
}

// ---------------------------------------------------------------------------
// HMMA GEMM: C[M, Nout](fp32) = A[M, KT](bf16) @ B[Nout, KT](bf16)^T + bias
// Round-9 config: CTA 128x128, 4 warps (2x2), warp tile 64x64, K-chunk 32,
// 4-stage cp.async, 80B row stride, one barrier per K-chunk.
// A is stored deduped ([Ah|Al], stride KTA); logical chunk kc>=32 reads
// physical chunk kc-32 (region 3 == region 1). Measured neutral on GEMM time.
// ---------------------------------------------------------------------------
__global__ __launch_bounds__(128, 2)
void gemm_mma(const __nv_bfloat16* __restrict__ A,
              const __nv_bfloat16* __restrict__ Bm,
              const float* __restrict__ bias, float* __restrict__ C, int Nout)
{
    extern __shared__ __align__(128) char smem[];
    const int tid  = threadIdx.x;
    const int wid  = tid >> 5;
    const int lane = tid & 31;
    const int m0 = blockIdx.y * BM;
    const int n0 = blockIdx.x * BN;
    const int warp_m = (wid >> 1) * 64;   // 0 or 64
    const int warp_n = (wid & 1) * 64;    // 0 or 64
    const uint32_t sbase = smem_u32(smem);

    // load thread mapping: 512 16B-chunks per tile, 4 per thread per tile
    const int lr = tid >> 2;        // 0..31 base row
    const int lc = tid & 3;         // 16B chunk in row

    float acc[4][8][4];
#pragma unroll
    for (int mi = 0; mi < 4; mi++)
#pragma unroll
        for (int ni = 0; ni < 8; ni++)
#pragma unroll
            for (int r = 0; r < 4; r++) acc[mi][ni][r] = 0.f;

    auto load_stage = [&](int kc, int buf) {
        const uint32_t as = sbase + buf * ST_BYTES;
        const uint32_t bs = as + A_ST;
        const int kca = (kc < 32) ? kc : kc - 32;   // A region-3 dedup remap
        const __nv_bfloat16* Ag = A  + (size_t)m0 * KTA + kca * BK;
        const __nv_bfloat16* Bg = Bm + (size_t)n0 * KT  + kc  * BK;
#pragma unroll
        for (int i = 0; i < 4; i++) {
            int r = lr + i * 32;
            cp_async16(as + r * ROWB + lc * 16, Ag + (size_t)r * KTA + lc * 8);
        }
#pragma unroll
        for (int i = 0; i < 4; i++) {
            int r = lr + i * 32;
            cp_async16(bs + r * ROWB + lc * 16, Bg + (size_t)r * KT + lc * 8);
        }
        CP_COMMIT();
    };

    load_stage(0, 0);
    load_stage(1, 1);
    load_stage(2, 2);

    // fragment addresses (constant per thread, add stage/k offsets)
    const uint32_t a_addr0 = sbase + (warp_m + (lane & 15)) * ROWB + (lane >> 4) * 16;
    const uint32_t b_addr0 = sbase + A_ST
                           + (warp_n + ((lane >> 4) << 3) + (lane & 7)) * ROWB
                           + (((lane >> 3) & 1) << 4);

    for (int k = 0; k < NK; k++) {
        const int buf = k & 3;
        if (k < NK - 2)       { CP_WAIT(2); }
        else if (k == NK - 2) { CP_WAIT(1); }
        else                  { CP_WAIT(0); }
        __syncthreads();

        const uint32_t soff = buf * ST_BYTES;
#pragma unroll
        for (int ks = 0; ks < 2; ks++) {            // two k16 steps per chunk
            uint32_t af[4][4], bf[4][4];
#pragma unroll
            for (int mi = 0; mi < 4; mi++)
                ldsm4(af[mi], a_addr0 + soff + mi * 16 * ROWB + ks * 32);
#pragma unroll
            for (int nj = 0; nj < 4; nj++)
                ldsm4(bf[nj], b_addr0 + soff + nj * 16 * ROWB + ks * 32);
#pragma unroll
            for (int mi = 0; mi < 4; mi++) {
#pragma unroll
                for (int ni = 0; ni < 8; ni++) {
                    const uint32_t* bp = &bf[ni >> 1][(ni & 1) * 2];
                    mma16816(acc[mi][ni], af[mi], bp);
                }
            }
        }
        // no trailing barrier: iter-k writes target buf (k+3)&3 = (k-1)&3,
        // whose readers (iter k-1 ldsm) all passed this iter's top barrier.
        const int kn = k + 3;
        if (kn < NK) load_stage(kn, kn & 3);
    }

    // epilogue: bias + fp32 store (float2 per reg-pair)
#pragma unroll
    for (int mi = 0; mi < 4; mi++) {
#pragma unroll
        for (int ni = 0; ni < 8; ni++) {
            int row = m0 + warp_m + mi * 16 + (lane >> 2);
            int col = n0 + warp_n + ni * 8 + (lane & 3) * 2;
            float b0 = bias[col], b1 = bias[col + 1];
            float2 v0 = make_float2(acc[mi][ni][0] + b0, acc[mi][ni][1] + b1);
            float2 v1 = make_float2(acc[mi][ni][2] + b0, acc[mi][ni][3] + b1);
            *(float2*)(C + (size_t)row * Nout + col)       = v0;
            *(float2*)(C + (size_t)(row + 8) * Nout + col) = v1;
        }
    }
}

// ---------------------------------------------------------------------------
// Attention: one block per (b, h). 32 q x 32 k x 128 d.
//   - cp.async staging of q/k/v tiles (no register round trip)
//   - score phase: thread (q,dq) owns keys k = dq+4i (conflict-free LDS.128)
//   - REGISTER softmax: row max/sum via quad __shfl_xor (offsets 1,2);
//     no serial phase, no block barrier around softmax. Each thread stores
//     its 8 normalized probs; ctx reader of row q is the SAME warp, so a
//     __syncwarp() is sufficient. Exactly ONE __syncthreads in the kernel.
//   - ctx: thread owns dim chunks (dq+4jj)*4 (broadcast + conflict-free)
//   - direct bf16 [ch|cl] write (stride KTA)
// ---------------------------------------------------------------------------
#define AROW 132
#define SROW 36
__global__ __launch_bounds__(128)
void attn_kernel(const float* __restrict__ qkv,
                 const unsigned char* __restrict__ pad,
                 __nv_bfloat16* __restrict__ ctxa)
{
    __shared__ float qs[32 * AROW];
    __shared__ float ks[32 * AROW];
    __shared__ float vs[32 * AROW];
    __shared__ float sc[32 * SROW];
    __shared__ int   spad[32];

    const int b = blockIdx.x >> 2;
    const int h = blockIdx.x & 3;
    const int tid = threadIdx.x;

    const float* base = qkv + (size_t)b * N_ * QKV_COLS + h * HD_;

    // cp.async gmem -> smem staging (24 x 16B per thread)
    for (int u = tid; u < 32 * 32; u += 128) {
        int r  = u >> 5;
        int c4 = (u & 31) << 2;
        const float* brow = base + (size_t)r * QKV_COLS + c4;
        cp_async16(smem_u32(&qs[r * AROW + c4]), brow);
        cp_async16(smem_u32(&ks[r * AROW + c4]), brow + D_);
        cp_async16(smem_u32(&vs[r * AROW + c4]), brow + 2 * D_);
    }
    CP_COMMIT();
    if (tid < 32) spad[tid] = pad[b * N_ + tid];
    CP_WAIT(0);
    __syncthreads();

    const int q  = tid >> 2;
    const int dq = tid & 3;

    // scores: thread handles keys k = dq + 4*i, i = 0..7
    float acc[8];
#pragma unroll
    for (int i = 0; i < 8; i++) acc[i] = 0.f;

    for (int c0 = 0; c0 < HD_; c0 += 16) {
        float4 qv[4];
#pragma unroll
        for (int c = 0; c < 4; c++)
            qv[c] = *(const float4*)&qs[q * AROW + c0 + 4 * c];
#pragma unroll
        for (int i = 0; i < 8; i++) {
            const float* kr = &ks[(dq + 4 * i) * AROW + c0];
#pragma unroll
            for (int c = 0; c < 4; c++) {
                float4 kv = *(const float4*)&kr[4 * c];
                acc[i] += qv[c].x * kv.x;
                acc[i] += qv[c].y * kv.y;
                acc[i] += qv[c].z * kv.z;
                acc[i] += qv[c].w * kv.w;
            }
        }
    }

    const float scale = 0.08838834764831845f;  // 1/sqrt(128)
#pragma unroll
    for (int i = 0; i < 8; i++) {
        int k = dq + 4 * i;
        acc[i] = (k == q || spad[k]) ? -1e30f : acc[i] * scale;
    }

    // register softmax: quad-wide max/sum via shuffles (lanes q*4+dq; xor 1,2
    // stay inside the quad)
    float m = acc[0];
#pragma unroll
    for (int i = 1; i < 8; i++) m = fmaxf(m, acc[i]);
    m = fmaxf(m, __shfl_xor_sync(0xFFFFFFFFu, m, 1));
    m = fmaxf(m, __shfl_xor_sync(0xFFFFFFFFu, m, 2));

    float sum = 0.f;
#pragma unroll
    for (int i = 0; i < 8; i++) {
        acc[i] = __expf(acc[i] - m);
        sum += acc[i];
    }
    sum += __shfl_xor_sync(0xFFFFFFFFu, sum, 1);
    sum += __shfl_xor_sync(0xFFFFFFFFu, sum, 2);
    const float inv = 1.f / sum;

#pragma unroll
    for (int i = 0; i < 8; i++)
        sc[q * SROW + dq + 4 * i] = acc[i] * inv;
    __syncwarp();   // probs for row q written and read by the SAME warp

    // ctx: thread (q,dq) owns dim chunks (dq + 4*jj)*4, jj = 0..7
    float4 o[8];
#pragma unroll
    for (int jj = 0; jj < 8; jj++) o[jj] = make_float4(0.f, 0.f, 0.f, 0.f);

    for (int k = 0; k < 32; k++) {
        float p = sc[q * SROW + k];
        const float* vr = &vs[k * AROW];
#pragma unroll
        for (int jj = 0; jj < 8; jj++) {
            float4 vv = *(const float4*)&vr[(dq + 4 * jj) * 4];
            o[jj].x += p * vv.x;
            o[jj].y += p * vv.y;
            o[jj].z += p * vv.z;
            o[jj].w += p * vv.w;
        }
    }

    // direct bf16 write: [ch | cl] (stride KTA), row q, chunks (dq+4jj)*4
    __nv_bfloat16* outr = ctxa + (size_t)b * N_ * KTA + h * HD_ + (size_t)q * KTA;
#pragma unroll
    for (int jj = 0; jj < 8; jj++) {
        int d0 = (dq + 4 * jj) * 4;
        __nv_bfloat16 h0, h1, h2, h3, l0, l1, l2, l3;
        split_bf16(o[jj].x, h0, l0);
        split_bf16(o[jj].y, h1, l1);
        split_bf16(o[jj].z, h2, l2);
        split_bf16(o[jj].w, h3, l3);
        ((__nv_bfloat162*)(outr + d0))[0]       = __nv_bfloat162(h0, h1);
        ((__nv_bfloat162*)(outr + d0))[1]       = __nv_bfloat162(h2, h3);
        ((__nv_bfloat162*)(outr + 512 + d0))[0] = __nv_bfloat162(l0, l1);
        ((__nv_bfloat162*)(outr + 512 + d0))[1] = __nv_bfloat162(l2, l3);
    }
}

// ---------------------------------------------------------------------------
// Launch
// ---------------------------------------------------------------------------
extern "C" void kernel_launch(void* const* d_in, const int* in_sizes, int n_in,
                              void* d_out, int out_size)
{
    const float*         x     = (const float*)d_in[0];
    const unsigned char* pmask = (const unsigned char*)d_in[1];
    const float*         w_in  = (const float*)d_in[2];
    const float*         b_in  = (const float*)d_in[3];
    const float*         w_out = (const float*)d_in[4];
    const float*         b_out = (const float*)d_in[5];
    float*               out   = (float*)d_out;

    void *qkv_p, *xa_p, *ctxa_p, *wina_p, *wouta_p;
    cudaGetSymbolAddress(&qkv_p,   g_qkv);
    cudaGetSymbolAddress(&xa_p,    g_xa);
    cudaGetSymbolAddress(&ctxa_p,  g_ctxa);
    cudaGetSymbolAddress(&wina_p,  g_wina);
    cudaGetSymbolAddress(&wouta_p, g_wouta);
    float*         qkv   = (float*)qkv_p;
    __nv_bfloat16* xa    = (__nv_bfloat16*)xa_p;
    __nv_bfloat16* ctxa  = (__nv_bfloat16*)ctxa_p;
    __nv_bfloat16* wina  = (__nv_bfloat16*)wina_p;
    __nv_bfloat16* wouta = (__nv_bfloat16*)wouta_p;

    cudaFuncSetAttribute(gemm_mma, cudaFuncAttributeMaxDynamicSharedMemorySize,
                         GEMM_SMEM);

    // split-precision conversions
    {
        int t4 = M_ROWS * 128;
        conv_a<<<(t4 + 255) / 256, 256>>>(x, xa, t4);
    }
    {
        int t4 = QKV_COLS * 128;
        conv_b<<<(t4 + 255) / 256, 256>>>(w_in, wina, t4);
    }
    {
        int t4 = D_ * 128;
        conv_b<<<(t4 + 255) / 256, 256>>>(w_out, wouta, t4);
    }

    // 1) QKV projection: (32768 x 1536)
    {
        dim3 grid(QKV_COLS / BN, M_ROWS / BM);   // (12, 256)
        gemm_mma<<<grid, 128, GEMM_SMEM>>>(xa, wina, b_in, qkv, QKV_COLS);
    }

    // 2) attention (writes deduped bf16 ctx)
    attn_kernel<<<B_ * H_, 128>>>(qkv, pmask, ctxa);

    // 3) output projection: (32768 x 512)
    {
        dim3 grid(D_ / BN, M_ROWS / BM);         // (4, 256)
        gemm_mma<<<grid, 128, GEMM_SMEM>>>(ctxa, wouta, b_out, out, D_);
    }
}